// round 12
// baseline (speedup 1.0000x reference)
#include <cuda_runtime.h>
#include <cuda_fp16.h>
#include <mma.h>
#include <math.h>

using namespace nvcuda;

#define NN 50000
#define NPAD 50048         // 391 * 128, wmma padded
#define EE 800000
#define ETOT 850000        // EE + NN self loops
#define FIN 128
#define HIDC 32
#define HEADS 8
#define NG 64
#define F1 256             // HEADS*HIDC
#define FULLMASK 0xffffffffu
#define NB_SCAN ((NN + 1023) / 1024)   // 49
#define EB 831             // edge blocks: EB*256*4 >= ETOT
#define ESTRIDE (EB * 256)

// ---------------- scratch (static device memory; no allocs allowed) ----------
__device__ __half g_h1h[(size_t)NN * F1];      // x @ W1, fp16      [N,256]
__device__ __half g_out1h[(size_t)NPAD * F1];  // relu(gat1)+b1     [Npad,256] (pad rows stay 0)
__device__ __half g_h2h[(size_t)NPAD * HIDC];  // out1 @ W2, fp16   [Npad,32]
__device__ __half g_w2h[F1 * HIDC];            // W2 in fp16
__device__ float  g_als1[NN * HEADS];
__device__ float  g_ald1[NN * HEADS];
__device__ float  g_als2[NN];
__device__ float  g_ald2[NN];
__device__ int    g_deg[NN];
__device__ int    g_rowptr[NN + 1];
__device__ int    g_cursor[NN];
__device__ int    g_srcs[ETOT];
__device__ int    g_bsum[NB_SCAN];
__device__ int    g_boff[NB_SCAN];
__device__ float  g_sums[NG * HIDC];
__device__ int    g_cnts[NG];

// ---------------- zero + W2 fp16 convert -------------------------------------
__global__ void zero_kernel(const float* __restrict__ W2) {
    int i = blockIdx.x * blockDim.x + threadIdx.x;
    if (i < NN) g_deg[i] = 0;
    if (i < F1 * HIDC) g_w2h[i] = __float2half(W2[i]);
    if (i < NG * HIDC) g_sums[i] = 0.0f;
    if (i < NG) g_cnts[i] = 0;
}

// degree histogram (4 strided edges / thread) + graph-size histogram
__global__ void deg_kernel(const int* __restrict__ ei, const int* __restrict__ batch) {
    __shared__ int hist[NG];
    int tid = threadIdx.x;
    if (tid < NG) hist[tid] = 0;
    __syncthreads();
    int t = blockIdx.x * blockDim.x + tid;
    #pragma unroll
    for (int u = 0; u < 4; u++) {
        int i = t + u * ESTRIDE;
        if (i < ETOT) {
            int dst = (i < EE) ? ei[EE + i] : (i - EE);
            atomicAdd(&g_deg[dst], 1);
        }
    }
    if (t < NN) atomicAdd(&hist[batch[t]], 1);
    __syncthreads();
    if (tid < NG && hist[tid]) atomicAdd(&g_cnts[tid], hist[tid]);
}

// ---- 3-kernel scan ----------------------------------------------------------
__global__ void scan_blocks() {
    __shared__ int ws[32];
    int b = blockIdx.x, tid = threadIdx.x, lane = tid & 31, wid = tid >> 5;
    int i = b * 1024 + tid;
    int v = (i < NN) ? g_deg[i] : 0;
    int x = v;
    #pragma unroll
    for (int o = 1; o < 32; o <<= 1) { int t = __shfl_up_sync(FULLMASK, x, o); if (lane >= o) x += t; }
    if (lane == 31) ws[wid] = x;
    __syncthreads();
    if (wid == 0) {
        int w = ws[lane];
        #pragma unroll
        for (int o = 1; o < 32; o <<= 1) { int t = __shfl_up_sync(FULLMASK, w, o); if (lane >= o) w += t; }
        ws[lane] = w;
    }
    __syncthreads();
    int incl = x + (wid ? ws[wid - 1] : 0);
    if (i < NN) g_rowptr[i + 1] = incl;
    if (tid == 1023) g_bsum[b] = incl;
}

__global__ void scan_sums() {
    int lane = threadIdx.x;
    int run = 0;
    for (int base = 0; base < NB_SCAN; base += 32) {
        int idx = base + lane;
        int v = (idx < NB_SCAN) ? g_bsum[idx] : 0;
        int x = v;
        #pragma unroll
        for (int o = 1; o < 32; o <<= 1) { int t = __shfl_up_sync(FULLMASK, x, o); if (lane >= o) x += t; }
        if (idx < NB_SCAN) g_boff[idx] = run + x - v;
        run += __shfl_sync(FULLMASK, x, 31);
    }
}

__global__ void scan_apply() {
    int i = blockIdx.x * blockDim.x + threadIdx.x;
    if (i == 0) g_rowptr[0] = 0;
    if (i < NN) {
        int r = g_rowptr[i + 1] + g_boff[i >> 10];
        g_rowptr[i + 1] = r;
        g_cursor[i] = r - g_deg[i];
    }
}

__global__ void fill_kernel(const int* __restrict__ ei) {
    int t = blockIdx.x * blockDim.x + threadIdx.x;
    #pragma unroll
    for (int u = 0; u < 4; u++) {
        int i = t + u * ESTRIDE;
        if (i < ETOT) {
            int src, dst;
            if (i < EE) { src = ei[i]; dst = ei[EE + i]; }
            else        { src = i - EE; dst = i - EE; }
            int pos = atomicAdd(&g_cursor[dst], 1);
            g_srcs[pos] = src;
        }
    }
}

// ---------------- TF32 GEMM 1: g_h1h(fp16) = x @ W1, fused al1 (no atomics) --
__global__ void gemm1_tc(const float* __restrict__ A, const float* __restrict__ B,
                         const float* __restrict__ asrc, const float* __restrict__ adst) {
    constexpr int LDA = 36, LDB = 136, LDS = 20;   // LDS: multiple of 4 floats (16B)
    __shared__ float As[128 * LDA];
    __shared__ float Bs[32 * LDB];
    __shared__ float scr[8][16 * LDS];
    int tid = threadIdx.x;
    int lane = tid & 31;
    int warp = tid >> 5;
    int wm = warp & 3;
    int wn = warp >> 2;
    int row0 = blockIdx.y * 128;
    int col0 = blockIdx.x * 128;

    wmma::fragment<wmma::accumulator, 16, 16, 8, float> c[2][4];
    #pragma unroll
    for (int i = 0; i < 2; i++)
        #pragma unroll
        for (int j = 0; j < 4; j++) wmma::fill_fragment(c[i][j], 0.0f);

    for (int k0 = 0; k0 < FIN; k0 += 32) {
        #pragma unroll
        for (int it = 0; it < 4; it++) {
            int idx = tid + it * 256;
            int r = idx >> 3, c4 = idx & 7;
            float4 v = make_float4(0.f, 0.f, 0.f, 0.f);
            if (row0 + r < NN)
                v = *reinterpret_cast<const float4*>(A + (size_t)(row0 + r) * FIN + k0 + c4 * 4);
            float* p = &As[r * LDA + c4 * 4];
            p[0] = wmma::__float_to_tf32(v.x); p[1] = wmma::__float_to_tf32(v.y);
            p[2] = wmma::__float_to_tf32(v.z); p[3] = wmma::__float_to_tf32(v.w);
        }
        #pragma unroll
        for (int it = 0; it < 4; it++) {
            int idx = tid + it * 256;
            int r = idx >> 5, c4 = idx & 31;
            float4 v = *reinterpret_cast<const float4*>(B + (size_t)(k0 + r) * F1 + col0 + c4 * 4);
            float* p = &Bs[r * LDB + c4 * 4];
            p[0] = wmma::__float_to_tf32(v.x); p[1] = wmma::__float_to_tf32(v.y);
            p[2] = wmma::__float_to_tf32(v.z); p[3] = wmma::__float_to_tf32(v.w);
        }
        __syncthreads();
        #pragma unroll
        for (int ks = 0; ks < 4; ks++) {
            wmma::fragment<wmma::matrix_a, 16, 16, 8, wmma::precision::tf32, wmma::row_major> a[2];
            wmma::fragment<wmma::matrix_b, 16, 16, 8, wmma::precision::tf32, wmma::row_major> b[4];
            #pragma unroll
            for (int i = 0; i < 2; i++)
                wmma::load_matrix_sync(a[i], &As[(wm * 32 + i * 16) * LDA + ks * 8], LDA);
            #pragma unroll
            for (int j = 0; j < 4; j++)
                wmma::load_matrix_sync(b[j], &Bs[(ks * 8) * LDB + wn * 64 + j * 16], LDB);
            #pragma unroll
            for (int i = 0; i < 2; i++)
                #pragma unroll
                for (int j = 0; j < 4; j++)
                    wmma::mma_sync(c[i][j], a[i], b[j], c[i][j]);
        }
        __syncthreads();
    }
    // epilogue: fragments -> smem -> fp16 global + exact per-head logits.
    // head (32 cols) spans j-tile pairs {0,1} and {2,3}; lane pair (2k,2k+1)
    // covers the two 8-col strips of a 16-col tile row.
    #pragma unroll
    for (int i = 0; i < 2; i++) {
        int r = row0 + wm * 32 + i * 16 + (lane >> 1);
        float psum = 0.f, pdsum = 0.f;
        #pragma unroll
        for (int j = 0; j < 4; j++) {
            wmma::store_matrix_sync(&scr[warp][0], c[i][j], LDS, wmma::mem_row_major);
            __syncwarp();
            int cc = col0 + wn * 64 + j * 16 + (lane & 1) * 8;
            if (r < NN) {
                const float* sp = &scr[warp][(lane >> 1) * LDS + (lane & 1) * 8];
                __half2 h4[4];
                #pragma unroll
                for (int q = 0; q < 4; q++)
                    h4[q] = __floats2half2_rn(sp[2 * q], sp[2 * q + 1]);
                *reinterpret_cast<uint4*>(&g_h1h[(size_t)r * F1 + cc]) =
                    *reinterpret_cast<uint4*>(h4);
                int head = cc >> 5;
                int cb = cc & 31;
                #pragma unroll
                for (int q = 0; q < 8; q++) {
                    psum  += sp[q] * asrc[head * HIDC + cb + q];
                    pdsum += sp[q] * adst[head * HIDC + cb + q];
                }
            }
            __syncwarp();
            if (j & 1) {
                float ts = psum + __shfl_xor_sync(FULLMASK, psum, 1);
                float td = pdsum + __shfl_xor_sync(FULLMASK, pdsum, 1);
                if (r < NN && (lane & 1) == 0) {
                    int head = (col0 >> 5) + 2 * wn + (j >> 1);
                    g_als1[r * HEADS + head] = ts;
                    g_ald1[r * HEADS + head] = td;
                }
                psum = 0.f; pdsum = 0.f;
            }
        }
    }
}

// ---------------- FP16 GEMM 2: g_h2h = out1h @ W2(fp16), fused al2 -----------
__global__ void gemm2_tc(const float* __restrict__ as2, const float* __restrict__ ad2) {
    constexpr int LDA = 80, LDB = 40, LDS = 36;   // halfs / halfs / floats
    __shared__ __half As[128 * LDA];
    __shared__ __half Bs[64 * LDB];
    __shared__ float  scr[4][32 * LDS];
    int tid = threadIdx.x;     // 128 threads, 4 warps
    int lane = tid & 31;
    int warp = tid >> 5;
    int row0 = blockIdx.y * 128;

    wmma::fragment<wmma::accumulator, 16, 16, 16, float> c[2][2];
    #pragma unroll
    for (int i = 0; i < 2; i++)
        #pragma unroll
        for (int j = 0; j < 2; j++) wmma::fill_fragment(c[i][j], 0.0f);

    for (int k0 = 0; k0 < F1; k0 += 64) {
        #pragma unroll
        for (int it = 0; it < 8; it++) {
            int idx = tid + it * 128;
            int r = idx >> 3, c8 = idx & 7;
            *reinterpret_cast<uint4*>(&As[r * LDA + c8 * 8]) =
                *reinterpret_cast<const uint4*>(&g_out1h[(size_t)(row0 + r) * F1 + k0 + c8 * 8]);
        }
        #pragma unroll
        for (int it = 0; it < 2; it++) {
            int idx = tid + it * 128;
            int r = idx >> 2, c8 = idx & 3;
            *reinterpret_cast<uint4*>(&Bs[r * LDB + c8 * 8]) =
                *reinterpret_cast<const uint4*>(&g_w2h[(k0 + r) * HIDC + c8 * 8]);
        }
        __syncthreads();
        #pragma unroll
        for (int ks = 0; ks < 4; ks++) {
            wmma::fragment<wmma::matrix_a, 16, 16, 16, __half, wmma::row_major> a[2];
            wmma::fragment<wmma::matrix_b, 16, 16, 16, __half, wmma::row_major> b[2];
            #pragma unroll
            for (int i = 0; i < 2; i++)
                wmma::load_matrix_sync(a[i], &As[(warp * 32 + i * 16) * LDA + ks * 16], LDA);
            #pragma unroll
            for (int j = 0; j < 2; j++)
                wmma::load_matrix_sync(b[j], &Bs[(ks * 16) * LDB + j * 16], LDB);
            #pragma unroll
            for (int i = 0; i < 2; i++)
                #pragma unroll
                for (int j = 0; j < 2; j++)
                    wmma::mma_sync(c[i][j], a[i], b[j], c[i][j]);
        }
        __syncthreads();
    }
    #pragma unroll
    for (int i = 0; i < 2; i++)
        #pragma unroll
        for (int j = 0; j < 2; j++)
            wmma::store_matrix_sync(&scr[warp][(i * 16) * LDS + j * 16], c[i][j], LDS,
                                    wmma::mem_row_major);
    __syncwarp();
    {
        int r = row0 + warp * 32 + lane;
        const float* sp = &scr[warp][lane * LDS];
        __half2 h2o[16];
        float ps = 0.f, pd = 0.f;
        #pragma unroll
        for (int q = 0; q < 16; q++) {
            float vx = sp[2 * q], vy = sp[2 * q + 1];
            h2o[q] = __floats2half2_rn(vx, vy);
            ps += vx * as2[2 * q] + vy * as2[2 * q + 1];
            pd += vx * ad2[2 * q] + vy * ad2[2 * q + 1];
        }
        #pragma unroll
        for (int q = 0; q < 4; q++)
            *reinterpret_cast<uint4*>(&g_h2h[(size_t)r * HIDC + q * 8]) =
                *reinterpret_cast<uint4*>(&h2o[q * 4]);
        if (r < NN) { g_als2[r] = ps; g_ald2[r] = pd; }
    }
}

// ---------------- GAT layer 1: uint4 gather (1 load / lane / edge) -----------
// lane -> (head = lane>>2, colgroup = lane&3): owns cols [lane*8, lane*8+8).
__global__ void atten1_kernel(const float* __restrict__ bias) {
    __shared__ float s_w[8][32][9];   // [warp][edge-in-chunk][head] padded
    int node = (blockIdx.x * blockDim.x + threadIdx.x) >> 5;
    int lane = threadIdx.x & 31;
    int warp = (threadIdx.x >> 5) & 7;
    if (node >= NN) return;
    int start = g_rowptr[node], end = g_rowptr[node + 1];
    int hsel = lane >> 2;

    float ad[8];
    #pragma unroll
    for (int h = 0; h < 8; h++) ad[h] = g_ald1[node * 8 + h];

    float acc[8];
    #pragma unroll
    for (int q = 0; q < 8; q++) acc[q] = 0.0f;
    float z[8];
    #pragma unroll
    for (int h = 0; h < 8; h++) z[h] = 0.0f;

    for (int i = start; i < end; i += 32) {
        int cnt = min(32, end - i);
        int sreg = (lane < cnt) ? g_srcs[i + lane] : 0;
        if (lane < cnt) {
            float4 a0 = *reinterpret_cast<const float4*>(g_als1 + (size_t)sreg * 8);
            float4 a1 = *reinterpret_cast<const float4*>(g_als1 + (size_t)sreg * 8 + 4);
            float av[8] = {a0.x, a0.y, a0.z, a0.w, a1.x, a1.y, a1.z, a1.w};
            #pragma unroll
            for (int h = 0; h < 8; h++) {
                float e = av[h] + ad[h];
                e = (e > 0.0f) ? e : 0.2f * e;
                float wv = __expf(e);
                s_w[warp][lane][h] = wv;
                z[h] += wv;
            }
        }
        __syncwarp();
        #pragma unroll 4
        for (int j = 0; j < cnt; j++) {
            int s = __shfl_sync(FULLMASK, sreg, j);
            float wv = s_w[warp][j][hsel];
            uint4 raw = *reinterpret_cast<const uint4*>(&g_h1h[(size_t)s * F1 + lane * 8]);
            const __half2* h2 = reinterpret_cast<const __half2*>(&raw);
            #pragma unroll
            for (int q = 0; q < 4; q++) {
                float2 f = __half22float2(h2[q]);
                acc[2 * q]     += wv * f.x;
                acc[2 * q + 1] += wv * f.y;
            }
        }
        __syncwarp();
    }
    // reduce z per head; distribute via smem (avoid dynamic register indexing)
    #pragma unroll
    for (int h = 0; h < 8; h++) {
        float zz = z[h];
        #pragma unroll
        for (int off = 16; off; off >>= 1) zz += __shfl_down_sync(FULLMASK, zz, off);
        if (lane == 0) s_w[warp][0][h] = 1.0f / zz;
    }
    __syncwarp();
    float iz = s_w[warp][0][hsel];
    float4 b0 = *reinterpret_cast<const float4*>(bias + lane * 8);
    float4 b1 = *reinterpret_cast<const float4*>(bias + lane * 8 + 4);
    float bv[8] = {b0.x, b0.y, b0.z, b0.w, b1.x, b1.y, b1.z, b1.w};
    __half2 h2o[4];
    #pragma unroll
    for (int q = 0; q < 4; q++) {
        float vx = fmaxf(acc[2 * q] * iz + bv[2 * q], 0.0f);
        float vy = fmaxf(acc[2 * q + 1] * iz + bv[2 * q + 1], 0.0f);
        h2o[q] = __floats2half2_rn(vx, vy);
    }
    *reinterpret_cast<uint4*>(&g_out1h[(size_t)node * F1 + lane * 8]) =
        *reinterpret_cast<uint4*>(h2o);
}

// ---------------- GAT layer 2: 8-edge-parallel uint4 gather + fused pool -----
// lane -> (edgeslot g = lane>>2, sub = lane&3): owns cols [sub*8, sub*8+8).
__global__ void atten2_kernel(const float* __restrict__ bias, const int* __restrict__ batch) {
    __shared__ float s_w[8][32];
    int node = (blockIdx.x * blockDim.x + threadIdx.x) >> 5;
    int lane = threadIdx.x & 31;
    int warp = (threadIdx.x >> 5) & 7;
    if (node >= NN) return;
    int start = g_rowptr[node], end = g_rowptr[node + 1];
    float ad = g_ald2[node];
    int g = lane >> 2, sub = lane & 3;

    float acc[8];
    #pragma unroll
    for (int q = 0; q < 8; q++) acc[q] = 0.0f;
    float z = 0.0f;

    for (int i = start; i < end; i += 32) {
        int cnt = min(32, end - i);
        int sreg = (lane < cnt) ? g_srcs[i + lane] : 0;
        if (lane < cnt) {
            float e = g_als2[sreg] + ad;
            e = (e > 0.0f) ? e : 0.2f * e;
            float wv = __expf(e);
            s_w[warp][lane] = wv;
            z += wv;
        }
        __syncwarp();
        for (int jj = 0; jj < cnt; jj += 8) {
            int e = jj + g;
            int s = __shfl_sync(FULLMASK, sreg, e & 31);
            float wv = (e < cnt) ? s_w[warp][e] : 0.0f;
            uint4 raw = *reinterpret_cast<const uint4*>(&g_h2h[(size_t)s * HIDC + sub * 8]);
            const __half2* h2 = reinterpret_cast<const __half2*>(&raw);
            #pragma unroll
            for (int q = 0; q < 4; q++) {
                float2 f = __half22float2(h2[q]);
                acc[2 * q]     += wv * f.x;
                acc[2 * q + 1] += wv * f.y;
            }
        }
        __syncwarp();
    }
    // combine edge slots (g dimension): lanes g*4+sub, xor over bits 2,3,4
    #pragma unroll
    for (int off = 4; off <= 16; off <<= 1)
        #pragma unroll
        for (int q = 0; q < 8; q++)
            acc[q] += __shfl_xor_sync(FULLMASK, acc[q], off);
    #pragma unroll
    for (int off = 16; off; off >>= 1) z += __shfl_down_sync(FULLMASK, z, off);
    float invz = 1.0f / __shfl_sync(FULLMASK, z, 0);

    if (g == 0) {
        int b = batch[node];
        #pragma unroll
        for (int q = 0; q < 8; q++) {
            float outv = acc[q] * invz + bias[sub * 8 + q];
            atomicAdd(&g_sums[b * HIDC + sub * 8 + q], outv);
        }
    }
}

__global__ void div_kernel(float* __restrict__ out) {
    int i = blockIdx.x * blockDim.x + threadIdx.x;
    if (i < NG * HIDC)
        out[i] = g_sums[i] / fmaxf((float)g_cnts[i / HIDC], 1.0f);
}

// ---------------- launch -----------------------------------------------------
extern "C" void kernel_launch(void* const* d_in, const int* in_sizes, int n_in,
                              void* d_out, int out_size) {
    const float* x   = (const float*)d_in[0];
    const int*   ei  = (const int*)d_in[1];
    // d_in[2] edge_attr: unused by reference (lin_edge=None)
    const int* batch = (const int*)d_in[3];
    const float* W1  = (const float*)d_in[4];
    const float* as1 = (const float*)d_in[5];
    const float* ad1 = (const float*)d_in[6];
    const float* b1  = (const float*)d_in[7];
    const float* W2  = (const float*)d_in[8];
    const float* as2 = (const float*)d_in[9];
    const float* ad2 = (const float*)d_in[10];
    const float* b2  = (const float*)d_in[11];
    float* out = (float*)d_out;

    const int WB = (NN * 32 + 255) / 256;   // warp-per-node grids (6250)
    const int MB = (NN + 127) / 128;        // 391

    zero_kernel<<<(NN + 255) / 256, 256>>>(W2);
    deg_kernel<<<EB, 256>>>(ei, batch);
    scan_blocks<<<NB_SCAN, 1024>>>();
    scan_sums<<<1, 32>>>();
    scan_apply<<<(NN + 255) / 256, 256>>>();
    fill_kernel<<<EB, 256>>>(ei);

    gemm1_tc<<<dim3(2, MB), 256>>>(x, W1, as1, ad1);
    atten1_kernel<<<WB, 256>>>(b1);

    gemm2_tc<<<dim3(1, MB), 128>>>(as2, ad2);
    atten2_kernel<<<WB, 256>>>(b2, batch);

    div_kernel<<<(NG * HIDC + 255) / 256, 256>>>(out);
}

// round 14
// speedup vs baseline: 1.7212x; 1.7212x over previous
#include <cuda_runtime.h>
#include <cuda_fp16.h>
#include <mma.h>
#include <math.h>

using namespace nvcuda;

#define NN 50000
#define NPAD 50048         // 391 * 128, wmma padded
#define EE 800000
#define ETOT 850000        // EE + NN self loops
#define FIN 128
#define HIDC 32
#define HEADS 8
#define NG 64
#define F1 256             // HEADS*HIDC
#define FULLMASK 0xffffffffu
#define NB_SCAN ((NN + 1023) / 1024)   // 49
#define EB 831             // edge blocks: EB*256*4 >= ETOT
#define ESTRIDE (EB * 256)

// ---------------- scratch (static device memory; no allocs allowed) ----------
__device__ __half g_h1h[(size_t)NN * F1];      // x @ W1, fp16      [N,256]
__device__ __half g_out1h[(size_t)NPAD * F1];  // relu(gat1)+b1     [Npad,256] (pad rows stay 0)
__device__ __half g_h2h[(size_t)NPAD * HIDC];  // out1 @ W2, fp16   [Npad,32]
__device__ __half g_w2h[F1 * HIDC];            // W2 in fp16
__device__ float  g_als1[NN * HEADS];
__device__ float  g_ald1[NN * HEADS];
__device__ float  g_als2[NN];
__device__ float  g_ald2[NN];
__device__ int    g_deg[NN];
__device__ int    g_rowptr[NN + 1];
__device__ int    g_cursor[NN];
__device__ int    g_srcs[ETOT];
__device__ int    g_bsum[NB_SCAN];
__device__ float  g_sums[NG * HIDC];
__device__ int    g_cnts[NG];

// ---------------- zero + W2 fp16 convert -------------------------------------
__global__ void zero_kernel(const float* __restrict__ W2) {
    int i = blockIdx.x * blockDim.x + threadIdx.x;
    if (i < NN) g_deg[i] = 0;
    if (i < F1 * HIDC) g_w2h[i] = __float2half(W2[i]);
    if (i < NG * HIDC) g_sums[i] = 0.0f;
    if (i < NG) g_cnts[i] = 0;
}

// degree histogram (4 strided edges / thread) + graph-size histogram
__global__ void deg_kernel(const int* __restrict__ ei, const int* __restrict__ batch) {
    __shared__ int hist[NG];
    int tid = threadIdx.x;
    if (tid < NG) hist[tid] = 0;
    __syncthreads();
    int t = blockIdx.x * blockDim.x + tid;
    #pragma unroll
    for (int u = 0; u < 4; u++) {
        int i = t + u * ESTRIDE;
        if (i < ETOT) {
            int dst = (i < EE) ? ei[EE + i] : (i - EE);
            atomicAdd(&g_deg[dst], 1);
        }
    }
    if (t < NN) atomicAdd(&hist[batch[t]], 1);
    __syncthreads();
    if (tid < NG && hist[tid]) atomicAdd(&g_cnts[tid], hist[tid]);
}

// ---- scan: block-local scan, then apply (partial-scan folded into apply) ----
__global__ void scan_blocks() {
    __shared__ int ws[32];
    int b = blockIdx.x, tid = threadIdx.x, lane = tid & 31, wid = tid >> 5;
    int i = b * 1024 + tid;
    int v = (i < NN) ? g_deg[i] : 0;
    int x = v;
    #pragma unroll
    for (int o = 1; o < 32; o <<= 1) { int t = __shfl_up_sync(FULLMASK, x, o); if (lane >= o) x += t; }
    if (lane == 31) ws[wid] = x;
    __syncthreads();
    if (wid == 0) {
        int w = ws[lane];
        #pragma unroll
        for (int o = 1; o < 32; o <<= 1) { int t = __shfl_up_sync(FULLMASK, w, o); if (lane >= o) w += t; }
        ws[lane] = w;
    }
    __syncthreads();
    int incl = x + (wid ? ws[wid - 1] : 0);
    if (i < NN) g_rowptr[i + 1] = incl;
    if (tid == 1023) g_bsum[b] = incl;
}

__global__ void scan_apply() {
    __shared__ int pref[64];
    int tid = threadIdx.x;
    if (tid < 32) {
        int lane = tid;
        int v0 = (lane < NB_SCAN) ? g_bsum[lane] : 0;
        int v1 = (lane + 32 < NB_SCAN) ? g_bsum[lane + 32] : 0;
        int x = v0;
        #pragma unroll
        for (int o = 1; o < 32; o <<= 1) { int t = __shfl_up_sync(FULLMASK, x, o); if (lane >= o) x += t; }
        pref[lane] = x - v0;                       // exclusive prefix, first 32
        int run = __shfl_sync(FULLMASK, x, 31);    // total of first 32
        int y = v1;
        #pragma unroll
        for (int o = 1; o < 32; o <<= 1) { int t = __shfl_up_sync(FULLMASK, y, o); if (lane >= o) y += t; }
        pref[32 + lane] = run + y - v1;
    }
    __syncthreads();
    int i = blockIdx.x * blockDim.x + tid;
    if (i == 0) g_rowptr[0] = 0;
    if (i < NN) {
        int r = g_rowptr[i + 1] + pref[i >> 10];
        g_rowptr[i + 1] = r;
        g_cursor[i] = r - g_deg[i];
    }
}

__global__ void fill_kernel(const int* __restrict__ ei) {
    int t = blockIdx.x * blockDim.x + threadIdx.x;
    #pragma unroll
    for (int u = 0; u < 4; u++) {
        int i = t + u * ESTRIDE;
        if (i < ETOT) {
            int src, dst;
            if (i < EE) { src = ei[i]; dst = ei[EE + i]; }
            else        { src = i - EE; dst = i - EE; }
            int pos = atomicAdd(&g_cursor[dst], 1);
            g_srcs[pos] = src;
        }
    }
}

// ---------------- TF32 GEMM 1: g_h1h(fp16) = x @ W1, fused al1 (no atomics) --
__global__ void gemm1_tc(const float* __restrict__ A, const float* __restrict__ B,
                         const float* __restrict__ asrc, const float* __restrict__ adst) {
    constexpr int LDA = 36, LDB = 136, LDS = 20;   // LDS: multiple of 4 floats (16B)
    __shared__ float As[128 * LDA];
    __shared__ float Bs[32 * LDB];
    __shared__ float scr[8][16 * LDS];
    int tid = threadIdx.x;
    int lane = tid & 31;
    int warp = tid >> 5;
    int wm = warp & 3;
    int wn = warp >> 2;
    int row0 = blockIdx.y * 128;
    int col0 = blockIdx.x * 128;

    wmma::fragment<wmma::accumulator, 16, 16, 8, float> c[2][4];
    #pragma unroll
    for (int i = 0; i < 2; i++)
        #pragma unroll
        for (int j = 0; j < 4; j++) wmma::fill_fragment(c[i][j], 0.0f);

    for (int k0 = 0; k0 < FIN; k0 += 32) {
        #pragma unroll
        for (int it = 0; it < 4; it++) {
            int idx = tid + it * 256;
            int r = idx >> 3, c4 = idx & 7;
            float4 v = make_float4(0.f, 0.f, 0.f, 0.f);
            if (row0 + r < NN)
                v = *reinterpret_cast<const float4*>(A + (size_t)(row0 + r) * FIN + k0 + c4 * 4);
            float* p = &As[r * LDA + c4 * 4];
            p[0] = wmma::__float_to_tf32(v.x); p[1] = wmma::__float_to_tf32(v.y);
            p[2] = wmma::__float_to_tf32(v.z); p[3] = wmma::__float_to_tf32(v.w);
        }
        #pragma unroll
        for (int it = 0; it < 4; it++) {
            int idx = tid + it * 256;
            int r = idx >> 5, c4 = idx & 31;
            float4 v = *reinterpret_cast<const float4*>(B + (size_t)(k0 + r) * F1 + col0 + c4 * 4);
            float* p = &Bs[r * LDB + c4 * 4];
            p[0] = wmma::__float_to_tf32(v.x); p[1] = wmma::__float_to_tf32(v.y);
            p[2] = wmma::__float_to_tf32(v.z); p[3] = wmma::__float_to_tf32(v.w);
        }
        __syncthreads();
        #pragma unroll
        for (int ks = 0; ks < 4; ks++) {
            wmma::fragment<wmma::matrix_a, 16, 16, 8, wmma::precision::tf32, wmma::row_major> a[2];
            wmma::fragment<wmma::matrix_b, 16, 16, 8, wmma::precision::tf32, wmma::row_major> b[4];
            #pragma unroll
            for (int i = 0; i < 2; i++)
                wmma::load_matrix_sync(a[i], &As[(wm * 32 + i * 16) * LDA + ks * 8], LDA);
            #pragma unroll
            for (int j = 0; j < 4; j++)
                wmma::load_matrix_sync(b[j], &Bs[(ks * 8) * LDB + wn * 64 + j * 16], LDB);
            #pragma unroll
            for (int i = 0; i < 2; i++)
                #pragma unroll
                for (int j = 0; j < 4; j++)
                    wmma::mma_sync(c[i][j], a[i], b[j], c[i][j]);
        }
        __syncthreads();
    }
    // epilogue: fragments -> smem -> fp16 global + exact per-head logits
    #pragma unroll
    for (int i = 0; i < 2; i++) {
        int r = row0 + wm * 32 + i * 16 + (lane >> 1);
        float psum = 0.f, pdsum = 0.f;
        #pragma unroll
        for (int j = 0; j < 4; j++) {
            wmma::store_matrix_sync(&scr[warp][0], c[i][j], LDS, wmma::mem_row_major);
            __syncwarp();
            int cc = col0 + wn * 64 + j * 16 + (lane & 1) * 8;
            if (r < NN) {
                const float* sp = &scr[warp][(lane >> 1) * LDS + (lane & 1) * 8];
                __half2 h4[4];
                #pragma unroll
                for (int q = 0; q < 4; q++)
                    h4[q] = __floats2half2_rn(sp[2 * q], sp[2 * q + 1]);
                *reinterpret_cast<uint4*>(&g_h1h[(size_t)r * F1 + cc]) =
                    *reinterpret_cast<uint4*>(h4);
                int head = cc >> 5;
                int cb = cc & 31;
                #pragma unroll
                for (int q = 0; q < 8; q++) {
                    psum  += sp[q] * asrc[head * HIDC + cb + q];
                    pdsum += sp[q] * adst[head * HIDC + cb + q];
                }
            }
            __syncwarp();
            if (j & 1) {
                float ts = psum + __shfl_xor_sync(FULLMASK, psum, 1);
                float td = pdsum + __shfl_xor_sync(FULLMASK, pdsum, 1);
                if (r < NN && (lane & 1) == 0) {
                    int head = (col0 >> 5) + 2 * wn + (j >> 1);
                    g_als1[r * HEADS + head] = ts;
                    g_ald1[r * HEADS + head] = td;
                }
                psum = 0.f; pdsum = 0.f;
            }
        }
    }
}

// ---------------- FP16 GEMM 2: g_h2h = out1h @ W2(fp16), fused al2 -----------
__global__ void gemm2_tc(const float* __restrict__ as2, const float* __restrict__ ad2) {
    constexpr int LDA = 80, LDB = 40, LDS = 36;   // halfs / halfs / floats
    __shared__ __half As[128 * LDA];
    __shared__ __half Bs[64 * LDB];
    __shared__ float  scr[4][32 * LDS];
    int tid = threadIdx.x;     // 128 threads, 4 warps
    int lane = tid & 31;
    int warp = tid >> 5;
    int row0 = blockIdx.y * 128;

    wmma::fragment<wmma::accumulator, 16, 16, 16, float> c[2][2];
    #pragma unroll
    for (int i = 0; i < 2; i++)
        #pragma unroll
        for (int j = 0; j < 2; j++) wmma::fill_fragment(c[i][j], 0.0f);

    for (int k0 = 0; k0 < F1; k0 += 64) {
        #pragma unroll
        for (int it = 0; it < 8; it++) {
            int idx = tid + it * 128;
            int r = idx >> 3, c8 = idx & 7;
            *reinterpret_cast<uint4*>(&As[r * LDA + c8 * 8]) =
                *reinterpret_cast<const uint4*>(&g_out1h[(size_t)(row0 + r) * F1 + k0 + c8 * 8]);
        }
        #pragma unroll
        for (int it = 0; it < 2; it++) {
            int idx = tid + it * 128;
            int r = idx >> 2, c8 = idx & 3;
            *reinterpret_cast<uint4*>(&Bs[r * LDB + c8 * 8]) =
                *reinterpret_cast<const uint4*>(&g_w2h[(k0 + r) * HIDC + c8 * 8]);
        }
        __syncthreads();
        #pragma unroll
        for (int ks = 0; ks < 4; ks++) {
            wmma::fragment<wmma::matrix_a, 16, 16, 16, __half, wmma::row_major> a[2];
            wmma::fragment<wmma::matrix_b, 16, 16, 16, __half, wmma::row_major> b[2];
            #pragma unroll
            for (int i = 0; i < 2; i++)
                wmma::load_matrix_sync(a[i], &As[(warp * 32 + i * 16) * LDA + ks * 16], LDA);
            #pragma unroll
            for (int j = 0; j < 2; j++)
                wmma::load_matrix_sync(b[j], &Bs[(ks * 16) * LDB + j * 16], LDB);
            #pragma unroll
            for (int i = 0; i < 2; i++)
                #pragma unroll
                for (int j = 0; j < 2; j++)
                    wmma::mma_sync(c[i][j], a[i], b[j], c[i][j]);
        }
        __syncthreads();
    }
    #pragma unroll
    for (int i = 0; i < 2; i++)
        #pragma unroll
        for (int j = 0; j < 2; j++)
            wmma::store_matrix_sync(&scr[warp][(i * 16) * LDS + j * 16], c[i][j], LDS,
                                    wmma::mem_row_major);
    __syncwarp();
    {
        int r = row0 + warp * 32 + lane;
        const float* sp = &scr[warp][lane * LDS];
        __half2 h2o[16];
        float ps = 0.f, pd = 0.f;
        #pragma unroll
        for (int q = 0; q < 16; q++) {
            float vx = sp[2 * q], vy = sp[2 * q + 1];
            h2o[q] = __floats2half2_rn(vx, vy);
            ps += vx * as2[2 * q] + vy * as2[2 * q + 1];
            pd += vx * ad2[2 * q] + vy * ad2[2 * q + 1];
        }
        #pragma unroll
        for (int q = 0; q < 4; q++)
            *reinterpret_cast<uint4*>(&g_h2h[(size_t)r * HIDC + q * 8]) =
                *reinterpret_cast<uint4*>(&h2o[q * 4]);
        if (r < NN) { g_als2[r] = ps; g_ald2[r] = pd; }
    }
}

// ---------------- GAT layer 1: single-pass softmax, narrow fp16 gather -------
// (narrow half2 loads: 1 line per LDG -> 1.0 cyc/wavefront at L1; do NOT widen)
__global__ void atten1_kernel(const float* __restrict__ bias) {
    __shared__ float s_w[8][32][9];   // [warp][edge-in-chunk][head] padded
    int node = (blockIdx.x * blockDim.x + threadIdx.x) >> 5;
    int lane = threadIdx.x & 31;
    int warp = (threadIdx.x >> 5) & 7;
    if (node >= NN) return;
    int start = g_rowptr[node], end = g_rowptr[node + 1];

    float ad[8];
    #pragma unroll
    for (int h = 0; h < 8; h++) ad[h] = g_ald1[node * 8 + h];

    int hsel = lane >> 4;
    float2 acc[4];
    #pragma unroll
    for (int p = 0; p < 4; p++) acc[p] = make_float2(0.f, 0.f);
    float z[8];
    #pragma unroll
    for (int h = 0; h < 8; h++) z[h] = 0.0f;
    const __half2* hbase = reinterpret_cast<const __half2*>(g_h1h);

    for (int i = start; i < end; i += 32) {
        int cnt = min(32, end - i);
        int sreg = (lane < cnt) ? g_srcs[i + lane] : 0;
        if (lane < cnt) {
            float4 a0 = *reinterpret_cast<const float4*>(g_als1 + (size_t)sreg * 8);
            float4 a1 = *reinterpret_cast<const float4*>(g_als1 + (size_t)sreg * 8 + 4);
            float av[8] = {a0.x, a0.y, a0.z, a0.w, a1.x, a1.y, a1.z, a1.w};
            #pragma unroll
            for (int h = 0; h < 8; h++) {
                float e = av[h] + ad[h];
                e = (e > 0.0f) ? e : 0.2f * e;
                float wv = __expf(e);
                s_w[warp][lane][h] = wv;
                z[h] += wv;
            }
        }
        __syncwarp();
        if (cnt == 32) {
            #pragma unroll 4
            for (int j = 0; j < 32; j++) {
                int s = __shfl_sync(FULLMASK, sreg, j);
                const __half2* hv = hbase + (size_t)s * 128 + lane;
                #pragma unroll
                for (int p = 0; p < 4; p++) {
                    float wv = s_w[warp][j][2 * p + hsel];
                    float2 f = __half22float2(hv[p * 32]);
                    acc[p].x += wv * f.x;
                    acc[p].y += wv * f.y;
                }
            }
        } else {
            #pragma unroll 4
            for (int j = 0; j < cnt; j++) {
                int s = __shfl_sync(FULLMASK, sreg, j);
                const __half2* hv = hbase + (size_t)s * 128 + lane;
                #pragma unroll
                for (int p = 0; p < 4; p++) {
                    float wv = s_w[warp][j][2 * p + hsel];
                    float2 f = __half22float2(hv[p * 32]);
                    acc[p].x += wv * f.x;
                    acc[p].y += wv * f.y;
                }
            }
        }
        __syncwarp();
    }
    // reduce z across lanes, broadcast
    float invz[8];
    #pragma unroll
    for (int h = 0; h < 8; h++) {
        float zz = z[h];
        #pragma unroll
        for (int off = 16; off; off >>= 1) zz += __shfl_down_sync(FULLMASK, zz, off);
        invz[h] = 1.0f / __shfl_sync(FULLMASK, zz, 0);
    }
    #pragma unroll
    for (int p = 0; p < 4; p++) {
        int c = p * 64 + 2 * lane;
        float iz = invz[2 * p + hsel];
        float vx = fmaxf(acc[p].x * iz + bias[c], 0.0f);
        float vy = fmaxf(acc[p].y * iz + bias[c + 1], 0.0f);
        reinterpret_cast<__half2*>(g_out1h)[(size_t)node * 128 + p * 32 + lane] =
            __floats2half2_rn(vx, vy);
    }
}

// ---------------- GAT layer 2 single-pass + fused mean-pool sums -------------
__global__ void atten2_kernel(const float* __restrict__ bias, const int* __restrict__ batch) {
    __shared__ float s_w[8][32];
    int node = (blockIdx.x * blockDim.x + threadIdx.x) >> 5;
    int lane = threadIdx.x & 31;
    int warp = (threadIdx.x >> 5) & 7;
    if (node >= NN) return;
    int start = g_rowptr[node], end = g_rowptr[node + 1];
    float ad = g_ald2[node];

    float acc = 0.0f, z = 0.0f;
    for (int i = start; i < end; i += 32) {
        int cnt = min(32, end - i);
        int sreg = (lane < cnt) ? g_srcs[i + lane] : 0;
        if (lane < cnt) {
            float e = g_als2[sreg] + ad;
            e = (e > 0.0f) ? e : 0.2f * e;
            float wv = __expf(e);
            s_w[warp][lane] = wv;
            z += wv;
        }
        __syncwarp();
        #pragma unroll 4
        for (int j = 0; j < cnt; j++) {
            int s = __shfl_sync(FULLMASK, sreg, j);
            acc += s_w[warp][j] * __half2float(g_h2h[(size_t)s * HIDC + lane]);
        }
        __syncwarp();
    }
    #pragma unroll
    for (int off = 16; off; off >>= 1) z += __shfl_down_sync(FULLMASK, z, off);
    float invz = 1.0f / __shfl_sync(FULLMASK, z, 0);

    float outv = acc * invz + bias[lane];
    atomicAdd(&g_sums[batch[node] * HIDC + lane], outv);
}

__global__ void div_kernel(float* __restrict__ out) {
    int i = blockIdx.x * blockDim.x + threadIdx.x;
    if (i < NG * HIDC)
        out[i] = g_sums[i] / fmaxf((float)g_cnts[i / HIDC], 1.0f);
}

// ---------------- launch -----------------------------------------------------
extern "C" void kernel_launch(void* const* d_in, const int* in_sizes, int n_in,
                              void* d_out, int out_size) {
    const float* x   = (const float*)d_in[0];
    const int*   ei  = (const int*)d_in[1];
    // d_in[2] edge_attr: unused by reference (lin_edge=None)
    const int* batch = (const int*)d_in[3];
    const float* W1  = (const float*)d_in[4];
    const float* as1 = (const float*)d_in[5];
    const float* ad1 = (const float*)d_in[6];
    const float* b1  = (const float*)d_in[7];
    const float* W2  = (const float*)d_in[8];
    const float* as2 = (const float*)d_in[9];
    const float* ad2 = (const float*)d_in[10];
    const float* b2  = (const float*)d_in[11];
    float* out = (float*)d_out;

    const int WB = (NN * 32 + 255) / 256;   // warp-per-node grids (6250)
    const int MB = (NN + 127) / 128;        // 391

    zero_kernel<<<(NN + 255) / 256, 256>>>(W2);
    deg_kernel<<<EB, 256>>>(ei, batch);
    scan_blocks<<<NB_SCAN, 1024>>>();
    scan_apply<<<(NN + 255) / 256, 256>>>();
    fill_kernel<<<EB, 256>>>(ei);

    gemm1_tc<<<dim3(2, MB), 256>>>(x, W1, as1, ad1);
    atten1_kernel<<<WB, 256>>>(b1);

    gemm2_tc<<<dim3(1, MB), 128>>>(as2, ad2);
    atten2_kernel<<<WB, 256>>>(b2, batch);

    div_kernel<<<(NG * HIDC + 255) / 256, 256>>>(out);
}

// round 16
// speedup vs baseline: 1.8081x; 1.0505x over previous
#include <cuda_runtime.h>
#include <cuda_fp16.h>
#include <mma.h>
#include <math.h>

using namespace nvcuda;

#define NN 50000
#define NPAD 50048         // 391 * 128, wmma padded
#define EE 800000
#define ETOT 850000        // EE + NN self loops
#define FIN 128
#define HIDC 32
#define HEADS 8
#define NG 64
#define F1 256             // HEADS*HIDC
#define FULLMASK 0xffffffffu
#define NB_SCAN ((NN + 1023) / 1024)   // 49
#define EB 831             // edge blocks: EB*256*4 >= ETOT
#define ESTRIDE (EB * 256)

// ---------------- scratch (static device memory; no allocs allowed) ----------
__device__ __half g_h1h[(size_t)NN * F1];      // x @ W1, fp16      [N,256]
__device__ __half g_out1h[(size_t)NPAD * F1];  // relu(gat1)+b1     [Npad,256] (pad rows stay 0)
__device__ __half g_h2h[(size_t)NPAD * HIDC];  // out1 @ W2, fp16   [Npad,32]
__device__ __half g_w2h[F1 * HIDC];            // W2 in fp16
__device__ float  g_als1[NN * HEADS];
__device__ float  g_ald1[NN * HEADS];
__device__ float  g_als2[NN];
__device__ float  g_ald2[NN];
__device__ int    g_deg[NN];
__device__ int    g_rowptr[NN + 1];
__device__ int    g_cursor[NN];
__device__ int    g_srcs[ETOT];
__device__ int    g_bsum[NB_SCAN];
__device__ float  g_sums[NG * HIDC];
__device__ int    g_cnts[NG];

// ---------------- zero + W2 fp16 convert -------------------------------------
__global__ void zero_kernel(const float* __restrict__ W2) {
    int i = blockIdx.x * blockDim.x + threadIdx.x;
    if (i < NN) g_deg[i] = 0;
    if (i < F1 * HIDC) g_w2h[i] = __float2half(W2[i]);
    if (i < NG * HIDC) g_sums[i] = 0.0f;
    if (i < NG) g_cnts[i] = 0;
}

// degree histogram (4 strided edges / thread) + graph-size histogram
__global__ void deg_kernel(const int* __restrict__ ei, const int* __restrict__ batch) {
    __shared__ int hist[NG];
    int tid = threadIdx.x;
    if (tid < NG) hist[tid] = 0;
    __syncthreads();
    int t = blockIdx.x * blockDim.x + tid;
    #pragma unroll
    for (int u = 0; u < 4; u++) {
        int i = t + u * ESTRIDE;
        if (i < ETOT) {
            int dst = (i < EE) ? ei[EE + i] : (i - EE);
            atomicAdd(&g_deg[dst], 1);
        }
    }
    if (t < NN) atomicAdd(&hist[batch[t]], 1);
    __syncthreads();
    if (tid < NG && hist[tid]) atomicAdd(&g_cnts[tid], hist[tid]);
}

// ---- scan: block-local scan, then apply (partial-scan folded into apply) ----
__global__ void scan_blocks() {
    __shared__ int ws[32];
    int b = blockIdx.x, tid = threadIdx.x, lane = tid & 31, wid = tid >> 5;
    int i = b * 1024 + tid;
    int v = (i < NN) ? g_deg[i] : 0;
    int x = v;
    #pragma unroll
    for (int o = 1; o < 32; o <<= 1) { int t = __shfl_up_sync(FULLMASK, x, o); if (lane >= o) x += t; }
    if (lane == 31) ws[wid] = x;
    __syncthreads();
    if (wid == 0) {
        int w = ws[lane];
        #pragma unroll
        for (int o = 1; o < 32; o <<= 1) { int t = __shfl_up_sync(FULLMASK, w, o); if (lane >= o) w += t; }
        ws[lane] = w;
    }
    __syncthreads();
    int incl = x + (wid ? ws[wid - 1] : 0);
    if (i < NN) g_rowptr[i + 1] = incl;
    if (tid == 1023) g_bsum[b] = incl;
}

__global__ void scan_apply() {
    __shared__ int pref[64];
    int tid = threadIdx.x;
    if (tid < 32) {
        int lane = tid;
        int v0 = (lane < NB_SCAN) ? g_bsum[lane] : 0;
        int v1 = (lane + 32 < NB_SCAN) ? g_bsum[lane + 32] : 0;
        int x = v0;
        #pragma unroll
        for (int o = 1; o < 32; o <<= 1) { int t = __shfl_up_sync(FULLMASK, x, o); if (lane >= o) x += t; }
        pref[lane] = x - v0;                       // exclusive prefix, first 32
        int run = __shfl_sync(FULLMASK, x, 31);    // total of first 32
        int y = v1;
        #pragma unroll
        for (int o = 1; o < 32; o <<= 1) { int t = __shfl_up_sync(FULLMASK, y, o); if (lane >= o) y += t; }
        pref[32 + lane] = run + y - v1;
    }
    __syncthreads();
    int i = blockIdx.x * blockDim.x + tid;
    if (i == 0) g_rowptr[0] = 0;
    if (i < NN) {
        int r = g_rowptr[i + 1] + pref[i >> 10];
        g_rowptr[i + 1] = r;
        g_cursor[i] = r - g_deg[i];
    }
}

__global__ void fill_kernel(const int* __restrict__ ei) {
    int t = blockIdx.x * blockDim.x + threadIdx.x;
    #pragma unroll
    for (int u = 0; u < 4; u++) {
        int i = t + u * ESTRIDE;
        if (i < ETOT) {
            int src, dst;
            if (i < EE) { src = ei[i]; dst = ei[EE + i]; }
            else        { src = i - EE; dst = i - EE; }
            int pos = atomicAdd(&g_cursor[dst], 1);
            g_srcs[pos] = src;
        }
    }
}

// ---------------- TF32 GEMM 1: g_h1h(fp16) = x @ W1, fused al1 (no atomics) --
__global__ void gemm1_tc(const float* __restrict__ A, const float* __restrict__ B,
                         const float* __restrict__ asrc, const float* __restrict__ adst) {
    constexpr int LDA = 36, LDB = 136, LDS = 20;   // LDS: multiple of 4 floats (16B)
    __shared__ float As[128 * LDA];
    __shared__ float Bs[32 * LDB];
    __shared__ float scr[8][16 * LDS];
    int tid = threadIdx.x;
    int lane = tid & 31;
    int warp = tid >> 5;
    int wm = warp & 3;
    int wn = warp >> 2;
    int row0 = blockIdx.y * 128;
    int col0 = blockIdx.x * 128;

    wmma::fragment<wmma::accumulator, 16, 16, 8, float> c[2][4];
    #pragma unroll
    for (int i = 0; i < 2; i++)
        #pragma unroll
        for (int j = 0; j < 4; j++) wmma::fill_fragment(c[i][j], 0.0f);

    for (int k0 = 0; k0 < FIN; k0 += 32) {
        #pragma unroll
        for (int it = 0; it < 4; it++) {
            int idx = tid + it * 256;
            int r = idx >> 3, c4 = idx & 7;
            float4 v = make_float4(0.f, 0.f, 0.f, 0.f);
            if (row0 + r < NN)
                v = *reinterpret_cast<const float4*>(A + (size_t)(row0 + r) * FIN + k0 + c4 * 4);
            float* p = &As[r * LDA + c4 * 4];
            p[0] = wmma::__float_to_tf32(v.x); p[1] = wmma::__float_to_tf32(v.y);
            p[2] = wmma::__float_to_tf32(v.z); p[3] = wmma::__float_to_tf32(v.w);
        }
        #pragma unroll
        for (int it = 0; it < 4; it++) {
            int idx = tid + it * 256;
            int r = idx >> 5, c4 = idx & 31;
            float4 v = *reinterpret_cast<const float4*>(B + (size_t)(k0 + r) * F1 + col0 + c4 * 4);
            float* p = &Bs[r * LDB + c4 * 4];
            p[0] = wmma::__float_to_tf32(v.x); p[1] = wmma::__float_to_tf32(v.y);
            p[2] = wmma::__float_to_tf32(v.z); p[3] = wmma::__float_to_tf32(v.w);
        }
        __syncthreads();
        #pragma unroll
        for (int ks = 0; ks < 4; ks++) {
            wmma::fragment<wmma::matrix_a, 16, 16, 8, wmma::precision::tf32, wmma::row_major> a[2];
            wmma::fragment<wmma::matrix_b, 16, 16, 8, wmma::precision::tf32, wmma::row_major> b[4];
            #pragma unroll
            for (int i = 0; i < 2; i++)
                wmma::load_matrix_sync(a[i], &As[(wm * 32 + i * 16) * LDA + ks * 8], LDA);
            #pragma unroll
            for (int j = 0; j < 4; j++)
                wmma::load_matrix_sync(b[j], &Bs[(ks * 8) * LDB + wn * 64 + j * 16], LDB);
            #pragma unroll
            for (int i = 0; i < 2; i++)
                #pragma unroll
                for (int j = 0; j < 4; j++)
                    wmma::mma_sync(c[i][j], a[i], b[j], c[i][j]);
        }
        __syncthreads();
    }
    // epilogue: fragments -> smem -> fp16 global + exact per-head logits
    #pragma unroll
    for (int i = 0; i < 2; i++) {
        int r = row0 + wm * 32 + i * 16 + (lane >> 1);
        float psum = 0.f, pdsum = 0.f;
        #pragma unroll
        for (int j = 0; j < 4; j++) {
            wmma::store_matrix_sync(&scr[warp][0], c[i][j], LDS, wmma::mem_row_major);
            __syncwarp();
            int cc = col0 + wn * 64 + j * 16 + (lane & 1) * 8;
            if (r < NN) {
                const float* sp = &scr[warp][(lane >> 1) * LDS + (lane & 1) * 8];
                __half2 h4[4];
                #pragma unroll
                for (int q = 0; q < 4; q++)
                    h4[q] = __floats2half2_rn(sp[2 * q], sp[2 * q + 1]);
                *reinterpret_cast<uint4*>(&g_h1h[(size_t)r * F1 + cc]) =
                    *reinterpret_cast<uint4*>(h4);
                int head = cc >> 5;
                int cb = cc & 31;
                #pragma unroll
                for (int q = 0; q < 8; q++) {
                    psum  += sp[q] * asrc[head * HIDC + cb + q];
                    pdsum += sp[q] * adst[head * HIDC + cb + q];
                }
            }
            __syncwarp();
            if (j & 1) {
                float ts = psum + __shfl_xor_sync(FULLMASK, psum, 1);
                float td = pdsum + __shfl_xor_sync(FULLMASK, pdsum, 1);
                if (r < NN && (lane & 1) == 0) {
                    int head = (col0 >> 5) + 2 * wn + (j >> 1);
                    g_als1[r * HEADS + head] = ts;
                    g_ald1[r * HEADS + head] = td;
                }
                psum = 0.f; pdsum = 0.f;
            }
        }
    }
}

// ---------------- FP16 GEMM 2: g_h2h = out1h @ W2(fp16), fused al2 -----------
__global__ void gemm2_tc(const float* __restrict__ as2, const float* __restrict__ ad2) {
    constexpr int LDA = 80, LDB = 40, LDS = 36;   // halfs / halfs / floats
    __shared__ __half As[128 * LDA];
    __shared__ __half Bs[64 * LDB];
    __shared__ float  scr[4][32 * LDS];
    int tid = threadIdx.x;     // 128 threads, 4 warps
    int lane = tid & 31;
    int warp = tid >> 5;
    int row0 = blockIdx.y * 128;

    wmma::fragment<wmma::accumulator, 16, 16, 16, float> c[2][2];
    #pragma unroll
    for (int i = 0; i < 2; i++)
        #pragma unroll
        for (int j = 0; j < 2; j++) wmma::fill_fragment(c[i][j], 0.0f);

    for (int k0 = 0; k0 < F1; k0 += 64) {
        #pragma unroll
        for (int it = 0; it < 8; it++) {
            int idx = tid + it * 128;
            int r = idx >> 3, c8 = idx & 7;
            *reinterpret_cast<uint4*>(&As[r * LDA + c8 * 8]) =
                *reinterpret_cast<const uint4*>(&g_out1h[(size_t)(row0 + r) * F1 + k0 + c8 * 8]);
        }
        #pragma unroll
        for (int it = 0; it < 2; it++) {
            int idx = tid + it * 128;
            int r = idx >> 2, c8 = idx & 3;
            *reinterpret_cast<uint4*>(&Bs[r * LDB + c8 * 8]) =
                *reinterpret_cast<const uint4*>(&g_w2h[(k0 + r) * HIDC + c8 * 8]);
        }
        __syncthreads();
        #pragma unroll
        for (int ks = 0; ks < 4; ks++) {
            wmma::fragment<wmma::matrix_a, 16, 16, 16, __half, wmma::row_major> a[2];
            wmma::fragment<wmma::matrix_b, 16, 16, 16, __half, wmma::row_major> b[2];
            #pragma unroll
            for (int i = 0; i < 2; i++)
                wmma::load_matrix_sync(a[i], &As[(warp * 32 + i * 16) * LDA + ks * 16], LDA);
            #pragma unroll
            for (int j = 0; j < 2; j++)
                wmma::load_matrix_sync(b[j], &Bs[(ks * 16) * LDB + j * 16], LDB);
            #pragma unroll
            for (int i = 0; i < 2; i++)
                #pragma unroll
                for (int j = 0; j < 2; j++)
                    wmma::mma_sync(c[i][j], a[i], b[j], c[i][j]);
        }
        __syncthreads();
    }
    #pragma unroll
    for (int i = 0; i < 2; i++)
        #pragma unroll
        for (int j = 0; j < 2; j++)
            wmma::store_matrix_sync(&scr[warp][(i * 16) * LDS + j * 16], c[i][j], LDS,
                                    wmma::mem_row_major);
    __syncwarp();
    {
        int r = row0 + warp * 32 + lane;
        const float* sp = &scr[warp][lane * LDS];
        __half2 h2o[16];
        float ps = 0.f, pd = 0.f;
        #pragma unroll
        for (int q = 0; q < 16; q++) {
            float vx = sp[2 * q], vy = sp[2 * q + 1];
            h2o[q] = __floats2half2_rn(vx, vy);
            ps += vx * as2[2 * q] + vy * as2[2 * q + 1];
            pd += vx * ad2[2 * q] + vy * ad2[2 * q + 1];
        }
        #pragma unroll
        for (int q = 0; q < 4; q++)
            *reinterpret_cast<uint4*>(&g_h2h[(size_t)r * HIDC + q * 8]) =
                *reinterpret_cast<uint4*>(&h2o[q * 4]);
        if (r < NN) { g_als2[r] = ps; g_ald2[r] = pd; }
    }
}

// ---------------- GAT layer 1: single-pass softmax, narrow fp16 gather -------
// (narrow half2 loads: 1 line per LDG -> 1.0 cyc/wavefront at L1; do NOT widen)
__global__ void atten1_kernel(const float* __restrict__ bias) {
    __shared__ float s_w[8][32][9];   // [warp][edge-in-chunk][head] padded
    int node = (blockIdx.x * blockDim.x + threadIdx.x) >> 5;
    int lane = threadIdx.x & 31;
    int warp = (threadIdx.x >> 5) & 7;
    if (node >= NN) return;
    int start = g_rowptr[node], end = g_rowptr[node + 1];

    float ad[8];
    #pragma unroll
    for (int h = 0; h < 8; h++) ad[h] = g_ald1[node * 8 + h];

    int hsel = lane >> 4;
    float2 acc[4];
    #pragma unroll
    for (int p = 0; p < 4; p++) acc[p] = make_float2(0.f, 0.f);
    float z[8];
    #pragma unroll
    for (int h = 0; h < 8; h++) z[h] = 0.0f;
    const __half2* hbase = reinterpret_cast<const __half2*>(g_h1h);

    for (int i = start; i < end; i += 32) {
        int cnt = min(32, end - i);
        int sreg = (lane < cnt) ? g_srcs[i + lane] : 0;
        if (lane < cnt) {
            float4 a0 = *reinterpret_cast<const float4*>(g_als1 + (size_t)sreg * 8);
            float4 a1 = *reinterpret_cast<const float4*>(g_als1 + (size_t)sreg * 8 + 4);
            float av[8] = {a0.x, a0.y, a0.z, a0.w, a1.x, a1.y, a1.z, a1.w};
            #pragma unroll
            for (int h = 0; h < 8; h++) {
                float e = av[h] + ad[h];
                e = (e > 0.0f) ? e : 0.2f * e;
                float wv = __expf(e);
                s_w[warp][lane][h] = wv;
                z[h] += wv;
            }
        }
        __syncwarp();
        if (cnt == 32) {
            #pragma unroll 4
            for (int j = 0; j < 32; j++) {
                int s = __shfl_sync(FULLMASK, sreg, j);
                const __half2* hv = hbase + (size_t)s * 128 + lane;
                #pragma unroll
                for (int p = 0; p < 4; p++) {
                    float wv = s_w[warp][j][2 * p + hsel];
                    float2 f = __half22float2(hv[p * 32]);
                    acc[p].x += wv * f.x;
                    acc[p].y += wv * f.y;
                }
            }
        } else {
            #pragma unroll 4
            for (int j = 0; j < cnt; j++) {
                int s = __shfl_sync(FULLMASK, sreg, j);
                const __half2* hv = hbase + (size_t)s * 128 + lane;
                #pragma unroll
                for (int p = 0; p < 4; p++) {
                    float wv = s_w[warp][j][2 * p + hsel];
                    float2 f = __half22float2(hv[p * 32]);
                    acc[p].x += wv * f.x;
                    acc[p].y += wv * f.y;
                }
            }
        }
        __syncwarp();
    }
    // reduce z across lanes, broadcast
    float invz[8];
    #pragma unroll
    for (int h = 0; h < 8; h++) {
        float zz = z[h];
        #pragma unroll
        for (int off = 16; off; off >>= 1) zz += __shfl_down_sync(FULLMASK, zz, off);
        invz[h] = 1.0f / __shfl_sync(FULLMASK, zz, 0);
    }
    #pragma unroll
    for (int p = 0; p < 4; p++) {
        int c = p * 64 + 2 * lane;
        float iz = invz[2 * p + hsel];
        float vx = fmaxf(acc[p].x * iz + bias[c], 0.0f);
        float vy = fmaxf(acc[p].y * iz + bias[c + 1], 0.0f);
        reinterpret_cast<__half2*>(g_out1h)[(size_t)node * 128 + p * 32 + lane] =
            __floats2half2_rn(vx, vy);
    }
}

// ---------------- GAT layer 2 single-pass + fused mean-pool sums -------------
__global__ void atten2_kernel(const float* __restrict__ bias, const int* __restrict__ batch) {
    __shared__ float s_w[8][32];
    int node = (blockIdx.x * blockDim.x + threadIdx.x) >> 5;
    int lane = threadIdx.x & 31;
    int warp = (threadIdx.x >> 5) & 7;
    if (node >= NN) return;
    int start = g_rowptr[node], end = g_rowptr[node + 1];
    float ad = g_ald2[node];

    float acc = 0.0f, z = 0.0f;
    for (int i = start; i < end; i += 32) {
        int cnt = min(32, end - i);
        int sreg = (lane < cnt) ? g_srcs[i + lane] : 0;
        if (lane < cnt) {
            float e = g_als2[sreg] + ad;
            e = (e > 0.0f) ? e : 0.2f * e;
            float wv = __expf(e);
            s_w[warp][lane] = wv;
            z += wv;
        }
        __syncwarp();
        #pragma unroll 4
        for (int j = 0; j < cnt; j++) {
            int s = __shfl_sync(FULLMASK, sreg, j);
            acc += s_w[warp][j] * __half2float(g_h2h[(size_t)s * HIDC + lane]);
        }
        __syncwarp();
    }
    #pragma unroll
    for (int off = 16; off; off >>= 1) z += __shfl_down_sync(FULLMASK, z, off);
    float invz = 1.0f / __shfl_sync(FULLMASK, z, 0);

    float outv = acc * invz + bias[lane];
    atomicAdd(&g_sums[batch[node] * HIDC + lane], outv);
}

__global__ void div_kernel(float* __restrict__ out) {
    int i = blockIdx.x * blockDim.x + threadIdx.x;
    if (i < NG * HIDC)
        out[i] = g_sums[i] / fmaxf((float)g_cnts[i / HIDC], 1.0f);
}

// ---------------- launch: fork CSR-build (default stream) vs gemm1 (s2) ------
extern "C" void kernel_launch(void* const* d_in, const int* in_sizes, int n_in,
                              void* d_out, int out_size) {
    const float* x   = (const float*)d_in[0];
    const int*   ei  = (const int*)d_in[1];
    // d_in[2] edge_attr: unused by reference (lin_edge=None)
    const int* batch = (const int*)d_in[3];
    const float* W1  = (const float*)d_in[4];
    const float* as1 = (const float*)d_in[5];
    const float* ad1 = (const float*)d_in[6];
    const float* b1  = (const float*)d_in[7];
    const float* W2  = (const float*)d_in[8];
    const float* as2 = (const float*)d_in[9];
    const float* ad2 = (const float*)d_in[10];
    const float* b2  = (const float*)d_in[11];
    float* out = (float*)d_out;

    // lazy one-time infra (no device memory involved; identical work per call)
    static cudaStream_t s2 = nullptr;
    static cudaEvent_t evF = nullptr, evJ = nullptr;
    if (s2 == nullptr) {
        cudaStreamCreateWithFlags(&s2, cudaStreamNonBlocking);
        cudaEventCreateWithFlags(&evF, cudaEventDisableTiming);
        cudaEventCreateWithFlags(&evJ, cudaEventDisableTiming);
    }

    const int WB = (NN * 32 + 255) / 256;   // warp-per-node grids (6250)
    const int MB = (NN + 127) / 128;        // 391

    // fork: gemm1 (independent of CSR build) on side stream
    cudaEventRecord(evF, 0);
    cudaStreamWaitEvent(s2, evF, 0);
    gemm1_tc<<<dim3(2, MB), 256, 0, s2>>>(x, W1, as1, ad1);
    cudaEventRecord(evJ, s2);

    // CSR build chain on the main (captured) stream
    zero_kernel<<<(NN + 255) / 256, 256>>>(W2);
    deg_kernel<<<EB, 256>>>(ei, batch);
    scan_blocks<<<NB_SCAN, 1024>>>();
    scan_apply<<<(NN + 255) / 256, 256>>>();
    fill_kernel<<<EB, 256>>>(ei);

    // join: atten1 needs CSR + h1h + als1/ald1
    cudaStreamWaitEvent(0, evJ, 0);
    atten1_kernel<<<WB, 256>>>(b1);

    gemm2_tc<<<dim3(1, MB), 128>>>(as2, ad2);
    atten2_kernel<<<WB, 256>>>(b2, batch);

    div_kernel<<<(NG * HIDC + 255) / 256, 256>>>(out);
}

// round 17
// speedup vs baseline: 1.8670x; 1.0326x over previous
#include <cuda_runtime.h>
#include <cuda_fp16.h>
#include <mma.h>
#include <math.h>

using namespace nvcuda;

#define NN 50000
#define NPAD 50048         // 391 * 128, wmma padded
#define EE 800000
#define ETOT 850000        // EE + NN self loops
#define FIN 128
#define HIDC 32
#define HEADS 8
#define NG 64
#define F1 256             // HEADS*HIDC
#define FULLMASK 0xffffffffu
#define NB_SCAN ((NN + 1023) / 1024)   // 49
#define EB 831             // edge blocks: EB*256*4 >= ETOT
#define ESTRIDE (EB * 256)

// ---------------- scratch (static device memory; no allocs allowed) ----------
// NOTE: g_deg, g_sums, g_cnts rely on .bss zero-init for the FIRST call and are
// re-zeroed by div_clean at the END of every call (self-cleaning across graph
// replays) — no dedicated zero kernel on the critical path.
__device__ __half g_h1h[(size_t)NN * F1];      // x @ W1, fp16      [N,256]
__device__ __half g_out1h[(size_t)NPAD * F1];  // relu(gat1)+b1     [Npad,256] (pad rows stay 0)
__device__ __half g_h2h[(size_t)NPAD * HIDC];  // out1 @ W2, fp16   [Npad,32]
__device__ __half g_w2h[F1 * HIDC];            // W2 in fp16
__device__ float  g_als1[NN * HEADS];
__device__ float  g_ald1[NN * HEADS];
__device__ float  g_als2[NN];
__device__ float  g_ald2[NN];
__device__ int    g_deg[NN];
__device__ int    g_rowptr[NN + 1];
__device__ int    g_cursor[NN];
__device__ int    g_srcs[ETOT];
__device__ int    g_bsum[NB_SCAN];
__device__ float  g_sums[NG * HIDC];
__device__ int    g_cnts[NG];

// degree histogram (4 strided edges / thread) + graph-size histogram
__global__ void deg_kernel(const int* __restrict__ ei, const int* __restrict__ batch) {
    __shared__ int hist[NG];
    int tid = threadIdx.x;
    if (tid < NG) hist[tid] = 0;
    __syncthreads();
    int t = blockIdx.x * blockDim.x + tid;
    #pragma unroll
    for (int u = 0; u < 4; u++) {
        int i = t + u * ESTRIDE;
        if (i < ETOT) {
            int dst = (i < EE) ? ei[EE + i] : (i - EE);
            atomicAdd(&g_deg[dst], 1);
        }
    }
    if (t < NN) atomicAdd(&hist[batch[t]], 1);
    __syncthreads();
    if (tid < NG && hist[tid]) atomicAdd(&g_cnts[tid], hist[tid]);
}

// ---- scan: block-local scan, then apply (partial-scan folded into apply) ----
__global__ void scan_blocks() {
    __shared__ int ws[32];
    int b = blockIdx.x, tid = threadIdx.x, lane = tid & 31, wid = tid >> 5;
    int i = b * 1024 + tid;
    int v = (i < NN) ? g_deg[i] : 0;
    int x = v;
    #pragma unroll
    for (int o = 1; o < 32; o <<= 1) { int t = __shfl_up_sync(FULLMASK, x, o); if (lane >= o) x += t; }
    if (lane == 31) ws[wid] = x;
    __syncthreads();
    if (wid == 0) {
        int w = ws[lane];
        #pragma unroll
        for (int o = 1; o < 32; o <<= 1) { int t = __shfl_up_sync(FULLMASK, w, o); if (lane >= o) w += t; }
        ws[lane] = w;
    }
    __syncthreads();
    int incl = x + (wid ? ws[wid - 1] : 0);
    if (i < NN) g_rowptr[i + 1] = incl;
    if (tid == 1023) g_bsum[b] = incl;
}

// scan of block partials folded in; also converts W2 -> fp16 using idle threads
__global__ void scan_apply(const float* __restrict__ W2) {
    __shared__ int pref[64];
    int tid = threadIdx.x;
    if (tid < 32) {
        int lane = tid;
        int v0 = (lane < NB_SCAN) ? g_bsum[lane] : 0;
        int v1 = (lane + 32 < NB_SCAN) ? g_bsum[lane + 32] : 0;
        int x = v0;
        #pragma unroll
        for (int o = 1; o < 32; o <<= 1) { int t = __shfl_up_sync(FULLMASK, x, o); if (lane >= o) x += t; }
        pref[lane] = x - v0;
        int run = __shfl_sync(FULLMASK, x, 31);
        int y = v1;
        #pragma unroll
        for (int o = 1; o < 32; o <<= 1) { int t = __shfl_up_sync(FULLMASK, y, o); if (lane >= o) y += t; }
        pref[32 + lane] = run + y - v1;
    }
    __syncthreads();
    int i = blockIdx.x * blockDim.x + tid;
    if (i == 0) g_rowptr[0] = 0;
    if (i < NN) {
        int r = g_rowptr[i + 1] + pref[i >> 10];
        g_rowptr[i + 1] = r;
        g_cursor[i] = r - g_deg[i];
    }
    if (i < F1 * HIDC) g_w2h[i] = __float2half(W2[i]);
}

__global__ void fill_kernel(const int* __restrict__ ei) {
    int t = blockIdx.x * blockDim.x + threadIdx.x;
    #pragma unroll
    for (int u = 0; u < 4; u++) {
        int i = t + u * ESTRIDE;
        if (i < ETOT) {
            int src, dst;
            if (i < EE) { src = ei[i]; dst = ei[EE + i]; }
            else        { src = i - EE; dst = i - EE; }
            int pos = atomicAdd(&g_cursor[dst], 1);
            g_srcs[pos] = src;
        }
    }
}

// ---------------- TF32 GEMM 1: g_h1h(fp16) = x @ W1, fused al1 (no atomics) --
__global__ void gemm1_tc(const float* __restrict__ A, const float* __restrict__ B,
                         const float* __restrict__ asrc, const float* __restrict__ adst) {
    constexpr int LDA = 36, LDB = 136, LDS = 20;   // LDS: multiple of 4 floats (16B)
    __shared__ float As[128 * LDA];
    __shared__ float Bs[32 * LDB];
    __shared__ float scr[8][16 * LDS];
    int tid = threadIdx.x;
    int lane = tid & 31;
    int warp = tid >> 5;
    int wm = warp & 3;
    int wn = warp >> 2;
    int row0 = blockIdx.y * 128;
    int col0 = blockIdx.x * 128;

    wmma::fragment<wmma::accumulator, 16, 16, 8, float> c[2][4];
    #pragma unroll
    for (int i = 0; i < 2; i++)
        #pragma unroll
        for (int j = 0; j < 4; j++) wmma::fill_fragment(c[i][j], 0.0f);

    for (int k0 = 0; k0 < FIN; k0 += 32) {
        #pragma unroll
        for (int it = 0; it < 4; it++) {
            int idx = tid + it * 256;
            int r = idx >> 3, c4 = idx & 7;
            float4 v = make_float4(0.f, 0.f, 0.f, 0.f);
            if (row0 + r < NN)
                v = *reinterpret_cast<const float4*>(A + (size_t)(row0 + r) * FIN + k0 + c4 * 4);
            float* p = &As[r * LDA + c4 * 4];
            p[0] = wmma::__float_to_tf32(v.x); p[1] = wmma::__float_to_tf32(v.y);
            p[2] = wmma::__float_to_tf32(v.z); p[3] = wmma::__float_to_tf32(v.w);
        }
        #pragma unroll
        for (int it = 0; it < 4; it++) {
            int idx = tid + it * 256;
            int r = idx >> 5, c4 = idx & 31;
            float4 v = *reinterpret_cast<const float4*>(B + (size_t)(k0 + r) * F1 + col0 + c4 * 4);
            float* p = &Bs[r * LDB + c4 * 4];
            p[0] = wmma::__float_to_tf32(v.x); p[1] = wmma::__float_to_tf32(v.y);
            p[2] = wmma::__float_to_tf32(v.z); p[3] = wmma::__float_to_tf32(v.w);
        }
        __syncthreads();
        #pragma unroll
        for (int ks = 0; ks < 4; ks++) {
            wmma::fragment<wmma::matrix_a, 16, 16, 8, wmma::precision::tf32, wmma::row_major> a[2];
            wmma::fragment<wmma::matrix_b, 16, 16, 8, wmma::precision::tf32, wmma::row_major> b[4];
            #pragma unroll
            for (int i = 0; i < 2; i++)
                wmma::load_matrix_sync(a[i], &As[(wm * 32 + i * 16) * LDA + ks * 8], LDA);
            #pragma unroll
            for (int j = 0; j < 4; j++)
                wmma::load_matrix_sync(b[j], &Bs[(ks * 8) * LDB + wn * 64 + j * 16], LDB);
            #pragma unroll
            for (int i = 0; i < 2; i++)
                #pragma unroll
                for (int j = 0; j < 4; j++)
                    wmma::mma_sync(c[i][j], a[i], b[j], c[i][j]);
        }
        __syncthreads();
    }
    // epilogue: fragments -> smem -> fp16 global + exact per-head logits
    #pragma unroll
    for (int i = 0; i < 2; i++) {
        int r = row0 + wm * 32 + i * 16 + (lane >> 1);
        float psum = 0.f, pdsum = 0.f;
        #pragma unroll
        for (int j = 0; j < 4; j++) {
            wmma::store_matrix_sync(&scr[warp][0], c[i][j], LDS, wmma::mem_row_major);
            __syncwarp();
            int cc = col0 + wn * 64 + j * 16 + (lane & 1) * 8;
            if (r < NN) {
                const float* sp = &scr[warp][(lane >> 1) * LDS + (lane & 1) * 8];
                __half2 h4[4];
                #pragma unroll
                for (int q = 0; q < 4; q++)
                    h4[q] = __floats2half2_rn(sp[2 * q], sp[2 * q + 1]);
                *reinterpret_cast<uint4*>(&g_h1h[(size_t)r * F1 + cc]) =
                    *reinterpret_cast<uint4*>(h4);
                int head = cc >> 5;
                int cb = cc & 31;
                #pragma unroll
                for (int q = 0; q < 8; q++) {
                    psum  += sp[q] * asrc[head * HIDC + cb + q];
                    pdsum += sp[q] * adst[head * HIDC + cb + q];
                }
            }
            __syncwarp();
            if (j & 1) {
                float ts = psum + __shfl_xor_sync(FULLMASK, psum, 1);
                float td = pdsum + __shfl_xor_sync(FULLMASK, pdsum, 1);
                if (r < NN && (lane & 1) == 0) {
                    int head = (col0 >> 5) + 2 * wn + (j >> 1);
                    g_als1[r * HEADS + head] = ts;
                    g_ald1[r * HEADS + head] = td;
                }
                psum = 0.f; pdsum = 0.f;
            }
        }
    }
}

// ---------------- FP16 GEMM 2: g_h2h = out1h @ W2(fp16), fused al2 -----------
__global__ void gemm2_tc(const float* __restrict__ as2, const float* __restrict__ ad2) {
    constexpr int LDA = 80, LDB = 40, LDS = 36;   // halfs / halfs / floats
    __shared__ __half As[128 * LDA];
    __shared__ __half Bs[64 * LDB];
    __shared__ float  scr[4][32 * LDS];
    int tid = threadIdx.x;     // 128 threads, 4 warps
    int lane = tid & 31;
    int warp = tid >> 5;
    int row0 = blockIdx.y * 128;

    wmma::fragment<wmma::accumulator, 16, 16, 16, float> c[2][2];
    #pragma unroll
    for (int i = 0; i < 2; i++)
        #pragma unroll
        for (int j = 0; j < 2; j++) wmma::fill_fragment(c[i][j], 0.0f);

    for (int k0 = 0; k0 < F1; k0 += 64) {
        #pragma unroll
        for (int it = 0; it < 8; it++) {
            int idx = tid + it * 128;
            int r = idx >> 3, c8 = idx & 7;
            *reinterpret_cast<uint4*>(&As[r * LDA + c8 * 8]) =
                *reinterpret_cast<const uint4*>(&g_out1h[(size_t)(row0 + r) * F1 + k0 + c8 * 8]);
        }
        #pragma unroll
        for (int it = 0; it < 2; it++) {
            int idx = tid + it * 128;
            int r = idx >> 2, c8 = idx & 3;
            *reinterpret_cast<uint4*>(&Bs[r * LDB + c8 * 8]) =
                *reinterpret_cast<const uint4*>(&g_w2h[(k0 + r) * HIDC + c8 * 8]);
        }
        __syncthreads();
        #pragma unroll
        for (int ks = 0; ks < 4; ks++) {
            wmma::fragment<wmma::matrix_a, 16, 16, 16, __half, wmma::row_major> a[2];
            wmma::fragment<wmma::matrix_b, 16, 16, 16, __half, wmma::row_major> b[2];
            #pragma unroll
            for (int i = 0; i < 2; i++)
                wmma::load_matrix_sync(a[i], &As[(warp * 32 + i * 16) * LDA + ks * 16], LDA);
            #pragma unroll
            for (int j = 0; j < 2; j++)
                wmma::load_matrix_sync(b[j], &Bs[(ks * 16) * LDB + j * 16], LDB);
            #pragma unroll
            for (int i = 0; i < 2; i++)
                #pragma unroll
                for (int j = 0; j < 2; j++)
                    wmma::mma_sync(c[i][j], a[i], b[j], c[i][j]);
        }
        __syncthreads();
    }
    #pragma unroll
    for (int i = 0; i < 2; i++)
        #pragma unroll
        for (int j = 0; j < 2; j++)
            wmma::store_matrix_sync(&scr[warp][(i * 16) * LDS + j * 16], c[i][j], LDS,
                                    wmma::mem_row_major);
    __syncwarp();
    {
        int r = row0 + warp * 32 + lane;
        const float* sp = &scr[warp][lane * LDS];
        __half2 h2o[16];
        float ps = 0.f, pd = 0.f;
        #pragma unroll
        for (int q = 0; q < 16; q++) {
            float vx = sp[2 * q], vy = sp[2 * q + 1];
            h2o[q] = __floats2half2_rn(vx, vy);
            ps += vx * as2[2 * q] + vy * as2[2 * q + 1];
            pd += vx * ad2[2 * q] + vy * ad2[2 * q + 1];
        }
        #pragma unroll
        for (int q = 0; q < 4; q++)
            *reinterpret_cast<uint4*>(&g_h2h[(size_t)r * HIDC + q * 8]) =
                *reinterpret_cast<uint4*>(&h2o[q * 4]);
        if (r < NN) { g_als2[r] = ps; g_ald2[r] = pd; }
    }
}

// ---------------- GAT layer 1: single-pass softmax, narrow fp16 gather -------
// (narrow half2 loads: 1 line per LDG -> 1.0 cyc/wavefront at L1; do NOT widen)
// weights stored [hsel][edge*4+p] so the gather reads ONE LDS.128 per edge.
__global__ void atten1_kernel(const float* __restrict__ bias) {
    __shared__ float s_w[8][2][128];   // [warp][hsel][edge*4+p]
    int node = (blockIdx.x * blockDim.x + threadIdx.x) >> 5;
    int lane = threadIdx.x & 31;
    int warp = (threadIdx.x >> 5) & 7;
    if (node >= NN) return;
    int start = g_rowptr[node], end = g_rowptr[node + 1];

    float ad[8];
    #pragma unroll
    for (int h = 0; h < 8; h++) ad[h] = g_ald1[node * 8 + h];

    int hsel = lane >> 4;
    float2 acc[4];
    #pragma unroll
    for (int p = 0; p < 4; p++) acc[p] = make_float2(0.f, 0.f);
    float z[8];
    #pragma unroll
    for (int h = 0; h < 8; h++) z[h] = 0.0f;
    const __half2* hbase = reinterpret_cast<const __half2*>(g_h1h);

    for (int i = start; i < end; i += 32) {
        int cnt = min(32, end - i);
        int sreg = (lane < cnt) ? g_srcs[i + lane] : 0;
        if (lane < cnt) {
            float4 a0 = *reinterpret_cast<const float4*>(g_als1 + (size_t)sreg * 8);
            float4 a1 = *reinterpret_cast<const float4*>(g_als1 + (size_t)sreg * 8 + 4);
            float av[8] = {a0.x, a0.y, a0.z, a0.w, a1.x, a1.y, a1.z, a1.w};
            float wv[8];
            #pragma unroll
            for (int h = 0; h < 8; h++) {
                float e = av[h] + ad[h];
                e = (e > 0.0f) ? e : 0.2f * e;
                wv[h] = __expf(e);
                z[h] += wv[h];
            }
            *reinterpret_cast<float4*>(&s_w[warp][0][lane * 4]) =
                make_float4(wv[0], wv[2], wv[4], wv[6]);
            *reinterpret_cast<float4*>(&s_w[warp][1][lane * 4]) =
                make_float4(wv[1], wv[3], wv[5], wv[7]);
        }
        __syncwarp();
        if (cnt == 32) {
            #pragma unroll 4
            for (int j = 0; j < 32; j++) {
                int s = __shfl_sync(FULLMASK, sreg, j);
                float4 w = *reinterpret_cast<const float4*>(&s_w[warp][hsel][j * 4]);
                const __half2* hv = hbase + (size_t)s * 128 + lane;
                float2 f0 = __half22float2(hv[0]);
                float2 f1 = __half22float2(hv[32]);
                float2 f2 = __half22float2(hv[64]);
                float2 f3 = __half22float2(hv[96]);
                acc[0].x += w.x * f0.x; acc[0].y += w.x * f0.y;
                acc[1].x += w.y * f1.x; acc[1].y += w.y * f1.y;
                acc[2].x += w.z * f2.x; acc[2].y += w.z * f2.y;
                acc[3].x += w.w * f3.x; acc[3].y += w.w * f3.y;
            }
        } else {
            #pragma unroll 4
            for (int j = 0; j < cnt; j++) {
                int s = __shfl_sync(FULLMASK, sreg, j);
                float4 w = *reinterpret_cast<const float4*>(&s_w[warp][hsel][j * 4]);
                const __half2* hv = hbase + (size_t)s * 128 + lane;
                float2 f0 = __half22float2(hv[0]);
                float2 f1 = __half22float2(hv[32]);
                float2 f2 = __half22float2(hv[64]);
                float2 f3 = __half22float2(hv[96]);
                acc[0].x += w.x * f0.x; acc[0].y += w.x * f0.y;
                acc[1].x += w.y * f1.x; acc[1].y += w.y * f1.y;
                acc[2].x += w.z * f2.x; acc[2].y += w.z * f2.y;
                acc[3].x += w.w * f3.x; acc[3].y += w.w * f3.y;
            }
        }
        __syncwarp();
    }
    // reduce z across lanes, broadcast
    float invz[8];
    #pragma unroll
    for (int h = 0; h < 8; h++) {
        float zz = z[h];
        #pragma unroll
        for (int off = 16; off; off >>= 1) zz += __shfl_down_sync(FULLMASK, zz, off);
        invz[h] = 1.0f / __shfl_sync(FULLMASK, zz, 0);
    }
    #pragma unroll
    for (int p = 0; p < 4; p++) {
        int c = p * 64 + 2 * lane;
        float iz = invz[2 * p + hsel];
        float vx = fmaxf(acc[p].x * iz + bias[c], 0.0f);
        float vy = fmaxf(acc[p].y * iz + bias[c + 1], 0.0f);
        reinterpret_cast<__half2*>(g_out1h)[(size_t)node * 128 + p * 32 + lane] =
            __floats2half2_rn(vx, vy);
    }
}

// ---------------- GAT layer 2 single-pass + fused mean-pool sums -------------
__global__ void atten2_kernel(const float* __restrict__ bias, const int* __restrict__ batch) {
    __shared__ float s_w[8][32];
    int node = (blockIdx.x * blockDim.x + threadIdx.x) >> 5;
    int lane = threadIdx.x & 31;
    int warp = (threadIdx.x >> 5) & 7;
    if (node >= NN) return;
    int start = g_rowptr[node], end = g_rowptr[node + 1];
    float ad = g_ald2[node];

    float acc = 0.0f, z = 0.0f;
    for (int i = start; i < end; i += 32) {
        int cnt = min(32, end - i);
        int sreg = (lane < cnt) ? g_srcs[i + lane] : 0;
        if (lane < cnt) {
            float e = g_als2[sreg] + ad;
            e = (e > 0.0f) ? e : 0.2f * e;
            float wv = __expf(e);
            s_w[warp][lane] = wv;
            z += wv;
        }
        __syncwarp();
        #pragma unroll 4
        for (int j = 0; j < cnt; j++) {
            int s = __shfl_sync(FULLMASK, sreg, j);
            acc += s_w[warp][j] * __half2float(g_h2h[(size_t)s * HIDC + lane]);
        }
        __syncwarp();
    }
    #pragma unroll
    for (int off = 16; off; off >>= 1) z += __shfl_down_sync(FULLMASK, z, off);
    float invz = 1.0f / __shfl_sync(FULLMASK, z, 0);

    float outv = acc * invz + bias[lane];
    atomicAdd(&g_sums[batch[node] * HIDC + lane], outv);
}

// output divide + self-clean (zero g_sums/g_cnts/g_deg for the next replay)
__global__ void div_clean(float* __restrict__ out) {
    int i = blockIdx.x * blockDim.x + threadIdx.x;
    if (blockIdx.x < (NG * HIDC) / 256) {          // blocks 0..7: i in [0, 2048)
        float s = g_sums[i];
        float c = (float)g_cnts[i >> 5];
        out[i] = s / fmaxf(c, 1.0f);
        g_sums[i] = 0.0f;
        __syncthreads();                           // all readers of these cnts are in-block
        if (threadIdx.x < 8) g_cnts[blockIdx.x * 8 + threadIdx.x] = 0;
    }
    if (i < NN) g_deg[i] = 0;
}

// ---------------- launch: fork CSR-build (default stream) vs gemm1 (s2) ------
extern "C" void kernel_launch(void* const* d_in, const int* in_sizes, int n_in,
                              void* d_out, int out_size) {
    const float* x   = (const float*)d_in[0];
    const int*   ei  = (const int*)d_in[1];
    // d_in[2] edge_attr: unused by reference (lin_edge=None)
    const int* batch = (const int*)d_in[3];
    const float* W1  = (const float*)d_in[4];
    const float* as1 = (const float*)d_in[5];
    const float* ad1 = (const float*)d_in[6];
    const float* b1  = (const float*)d_in[7];
    const float* W2  = (const float*)d_in[8];
    const float* as2 = (const float*)d_in[9];
    const float* ad2 = (const float*)d_in[10];
    const float* b2  = (const float*)d_in[11];
    float* out = (float*)d_out;

    // lazy one-time infra (no device memory involved; identical work per call)
    static cudaStream_t s2 = nullptr;
    static cudaEvent_t evF = nullptr, evJ = nullptr;
    if (s2 == nullptr) {
        cudaStreamCreateWithFlags(&s2, cudaStreamNonBlocking);
        cudaEventCreateWithFlags(&evF, cudaEventDisableTiming);
        cudaEventCreateWithFlags(&evJ, cudaEventDisableTiming);
    }

    const int WB = (NN * 32 + 255) / 256;   // warp-per-node grids (6250)
    const int MB = (NN + 127) / 128;        // 391

    // fork: gemm1 (independent of CSR build) on side stream
    cudaEventRecord(evF, 0);
    cudaStreamWaitEvent(s2, evF, 0);
    gemm1_tc<<<dim3(2, MB), 256, 0, s2>>>(x, W1, as1, ad1);
    cudaEventRecord(evJ, s2);

    // CSR build chain on the main (captured) stream (g_deg pre-zeroed)
    deg_kernel<<<EB, 256>>>(ei, batch);
    scan_blocks<<<NB_SCAN, 1024>>>();
    scan_apply<<<(NN + 255) / 256, 256>>>(W2);
    fill_kernel<<<EB, 256>>>(ei);

    // join: atten1 needs CSR + h1h + als1/ald1
    cudaStreamWaitEvent(0, evJ, 0);
    atten1_kernel<<<WB, 256>>>(b1);

    gemm2_tc<<<dim3(1, MB), 128>>>(as2, ad2);
    atten2_kernel<<<WB, 256>>>(b2, batch);

    div_clean<<<(NN + 255) / 256, 256>>>(out);
}